// round 8
// baseline (speedup 1.0000x reference)
#include <cuda_runtime.h>

// Uniform cubic B-spline via per-interval monomial (Horner) form.
// t = (x+1)*31.5, j = trunc(t) clamped to 62, u = t-j,
// out = p0[j] + u*(p1[j] + u*(p2[j] + u*p3[j])), with
//   p0=(c0+4c1+c2)/6, p1=(c2-c0)/2, p2=(c0-2c1+c2)/2, p3=(c3-c0+3(c1-c2))/6.
//
// R8: table lives in GLOBAL memory (1 KB, built once by a 64-thread setup
// kernel). Main kernel has no shared memory, no __syncthreads, no per-CTA
// init — gathers hit L1 (8 lines, hot). Occ-8, MLP=2 grid-stride (R5 shape).

#define NTBL 64                    // 63 intervals + 1 pad entry

__device__ float4 g_tbl[NTBL];

__global__ void build_table(const float* __restrict__ coeffs) {
    int j = threadIdx.x;           // 0..63
    if (j >= NTBL) return;
    int jj = min(j, 62);           // pad entry duplicates interval 62
    float c0 = coeffs[jj], c1 = coeffs[jj + 1], c2 = coeffs[jj + 2], c3 = coeffs[jj + 3];
    float4 p;
    p.x = fmaf(4.0f, c1, c0 + c2) * 0.16666666666666666f;
    p.y = (c2 - c0) * 0.5f;
    p.z = fmaf(-2.0f, c1, c0 + c2) * 0.5f;
    p.w = fmaf(3.0f, c1 - c2, c3 - c0) * 0.16666666666666666f;
    g_tbl[j] = p;
}

__device__ __forceinline__ float eval_one(float x) {
    float t = fmaf(x, 31.5f, 31.5f);
    int j = (int)t;                // t >= 0: truncation == floor
    j = min(j, 62);
    float u = t - (float)j;
    float4 p = __ldg(&g_tbl[j]);   // L1-hit gather, 8 lines total
    return fmaf(fmaf(fmaf(p.w, u, p.z), u, p.y), u, p.x);
}

__device__ __forceinline__ float4 eval_four(float4 xv) {
    float4 ov;
    ov.x = eval_one(xv.x);
    ov.y = eval_one(xv.y);
    ov.z = eval_one(xv.z);
    ov.w = eval_one(xv.w);
    return ov;
}

__global__ void __launch_bounds__(256, 8)
bspline_kernel(const float4* __restrict__ x4,
               float4* __restrict__ o4, int n4) {
    const int stride = gridDim.x * blockDim.x;
    int i = blockIdx.x * blockDim.x + threadIdx.x;

    // MLP=2: two independent float4 loads in flight; fits 32 regs.
    for (; i + stride < n4; i += 2 * stride) {
        float4 xa = x4[i];
        float4 xb = x4[i + stride];
        o4[i]          = eval_four(xa);
        o4[i + stride] = eval_four(xb);
    }
    if (i < n4) {
        float4 xa = x4[i];
        o4[i] = eval_four(xa);
    }
}

extern "C" void kernel_launch(void* const* d_in, const int* in_sizes, int n_in,
                              void* d_out, int out_size) {
    const float* x      = (const float*)d_in[0];
    const float* coeffs = (const float*)d_in[1];
    float* out = (float*)d_out;
    int n  = in_sizes[0];
    int n4 = n >> 2;                 // N = 2^22, divisible by 4
    build_table<<<1, 64>>>(coeffs);
    int threads = 256;
    int blocks  = 1184;              // 8 CTAs/SM x 148 SMs = one exact wave
    int max_blocks = (n4 + threads - 1) / threads;
    if (blocks > max_blocks) blocks = max_blocks;
    if (blocks < 1) blocks = 1;
    bspline_kernel<<<blocks, threads>>>((const float4*)x, (float4*)out, n4);
}

// round 9
// speedup vs baseline: 1.1866x; 1.1866x over previous
#include <cuda_runtime.h>

// Uniform cubic B-spline via per-interval monomial (Horner) form.
// t = (x+1)*31.5 in [0,63], j = trunc(t), u = t-j,
// out = p0[j] + u*(p1[j] + u*(p2[j] + u*p3[j])), with
//   p0=(c0+4c1+c2)/6, p1=(c2-c0)/2, p2=(c0-2c1+c2)/2, p3=(c3-c0+3(c1-c2))/6.
// Table padded to 64 entries (63 duplicates interval 62) -> no clamp needed.
//
// R9: setup kernel precomputes the monomial table in gmem; main kernel's
// prologue is 2 coalesced LDG.128 + 2 STS + one barrier (shortest possible
// serial startup). Shared table replicated 8x across the eight 16B bank
// groups -> every LDS.128 quarter-warp phase conflict-free. Occ-8, one exact
// wave, MLP=2 (proven R5 backbone).

#define REP  8
#define NTBL 64

__device__ float4 g_tbl[NTBL];

__global__ void build_table(const float* __restrict__ coeffs) {
    int j = threadIdx.x;                 // 0..63
    if (j >= NTBL) return;
    int jj = min(j, 62);                 // entry 63 duplicates interval 62
    float c0 = coeffs[jj], c1 = coeffs[jj + 1], c2 = coeffs[jj + 2], c3 = coeffs[jj + 3];
    float4 p;
    p.x = fmaf(4.0f, c1, c0 + c2) * 0.16666666666666666f;
    p.y = (c2 - c0) * 0.5f;
    p.z = fmaf(-2.0f, c1, c0 + c2) * 0.5f;
    p.w = fmaf(3.0f, c1 - c2, c3 - c0) * 0.16666666666666666f;
    g_tbl[j] = p;
}

__device__ __forceinline__ float eval_one(float x, const float4* __restrict__ tp) {
    float t = fmaf(x, 31.5f, 31.5f);     // in [0, 63]
    int j = (int)t;                      // trunc == floor; 0..63, table padded
    float u = t - (float)j;
    float4 p = tp[j * REP];              // tp pre-offset by lane's bank-group
    return fmaf(fmaf(fmaf(p.w, u, p.z), u, p.y), u, p.x);
}

__device__ __forceinline__ float4 eval_four(float4 xv, const float4* __restrict__ tp) {
    float4 ov;
    ov.x = eval_one(xv.x, tp);
    ov.y = eval_one(xv.y, tp);
    ov.z = eval_one(xv.z, tp);
    ov.w = eval_one(xv.w, tp);
    return ov;
}

__global__ void __launch_bounds__(256, 8)
bspline_kernel(const float4* __restrict__ x4,
               float4* __restrict__ o4, int n4) {
    __shared__ float4 tbl[NTBL * REP];
    int tid = threadIdx.x;
    // Lean prologue: 512 entries / 256 threads = 2 LDG.128 + 2 STS each.
    {
        float4 p0 = g_tbl[tid >> 3];             // entries 0..31 replicated
        float4 p1 = g_tbl[32 + (tid >> 3)];      // entries 32..63 replicated
        tbl[tid]       = p0;                     // (tid>>3)*8 + (tid&7)
        tbl[256 + tid] = p1;
    }
    __syncthreads();

    const float4* __restrict__ tp = tbl + (tid & (REP - 1));
    const int stride = gridDim.x * blockDim.x;
    int i = blockIdx.x * blockDim.x + tid;

    // MLP=2: two independent float4 loads in flight; fits 32 regs (R5).
    for (; i + stride < n4; i += 2 * stride) {
        float4 xa = x4[i];
        float4 xb = x4[i + stride];
        o4[i]          = eval_four(xa, tp);
        o4[i + stride] = eval_four(xb, tp);
    }
    if (i < n4) {
        float4 xa = x4[i];
        o4[i] = eval_four(xa, tp);
    }
}

extern "C" void kernel_launch(void* const* d_in, const int* in_sizes, int n_in,
                              void* d_out, int out_size) {
    const float* x      = (const float*)d_in[0];
    const float* coeffs = (const float*)d_in[1];
    float* out = (float*)d_out;
    int n  = in_sizes[0];
    int n4 = n >> 2;                 // N = 2^22, divisible by 4
    build_table<<<1, 64>>>(coeffs);
    int threads = 256;
    int blocks  = 1184;              // 8 CTAs/SM x 148 SMs = one exact wave
    int max_blocks = (n4 + threads - 1) / threads;
    if (blocks > max_blocks) blocks = max_blocks;
    if (blocks < 1) blocks = 1;
    bspline_kernel<<<blocks, threads>>>((const float4*)x, (float4*)out, n4);
}